// round 4
// baseline (speedup 1.0000x reference)
#include <cuda_runtime.h>
#include <cuda_bf16.h>
#include <math.h>

// ---------------- problem constants ----------------
#define BB   8
#define NN   8192
#define SS   2048
#define CFEAT 64
#define NSA0 16
#define NSA1 32
#define GST  68          // padded row stride for gathered input (67 cols)
#define EPSB 1e-5f

static constexpr int BS    = BB * SS;            // 16384
static constexpr int ROWS0 = BB * SS * NSA0;     // 262144
static constexpr int ROWS1 = BB * SS * NSA1;     // 524288

// ---------------- scratch (device globals; no allocation allowed) ----------------
__device__ int   g_fps[BS];
__device__ float g_nx[BS * 3];
__device__ int   g_idx0[ROWS0];
__device__ int   g_idx1[ROWS1];
__device__ float g_G[(size_t)ROWS1 * GST];
__device__ float g_Ya[(size_t)ROWS1 * 128];
__device__ float g_Yb[(size_t)ROWS1 * 128];
__device__ float g_Hcat[(size_t)BS * 256];
__device__ float g_Yh[(size_t)BS * 256];
__device__ float g_Yc[(size_t)BS * 256];
__device__ float g_part[(size_t)8192 * 128 * 2]; // max gridx=8192, K<=128 per y-slice... (K idx global)
__device__ float g_mean[256];
__device__ float g_istd[256];

// ---------------- FPS: one block per batch ----------------
__global__ __launch_bounds__(1024) void fps_kernel(const float* __restrict__ xyz,
                                                   int* __restrict__ out_idx)
{
    int b = blockIdx.x;
    const float* X = xyz + (size_t)b * NN * 3;
    int tid = threadIdx.x;

    float px[8], py[8], pz[8], dist[8];
    #pragma unroll
    for (int li = 0; li < 8; ++li) {
        int i = tid + 1024 * li;
        px[li] = X[i * 3 + 0];
        py[li] = X[i * 3 + 1];
        pz[li] = X[i * 3 + 2];
        dist[li] = 1e10f;
    }

    __shared__ float red_v[32];
    __shared__ int   red_i[32];
    __shared__ int   s_cur;
    if (tid == 0) s_cur = 0;
    __syncthreads();

    for (int it = 0; it < SS; ++it) {
        int cur = s_cur;
        if (tid == 0) out_idx[(size_t)b * SS + it] = cur;
        float lx = X[cur * 3 + 0];
        float ly = X[cur * 3 + 1];
        float lz = X[cur * 3 + 2];

        float best = -1.0f; int bi = 0;
        #pragma unroll
        for (int li = 0; li < 8; ++li) {
            float dx = px[li] - lx, dy = py[li] - ly, dz = pz[li] - lz;
            float d = dx * dx + dy * dy + dz * dz;
            float dd = fminf(dist[li], d);
            dist[li] = dd;
            if (dd > best) { best = dd; bi = tid + 1024 * li; }
        }
        #pragma unroll
        for (int off = 16; off; off >>= 1) {
            float ov = __shfl_down_sync(0xffffffffu, best, off);
            int   oi = __shfl_down_sync(0xffffffffu, bi, off);
            if (ov > best || (ov == best && oi < bi)) { best = ov; bi = oi; }
        }
        if ((tid & 31) == 0) { red_v[tid >> 5] = best; red_i[tid >> 5] = bi; }
        __syncthreads();
        if (tid < 32) {
            best = red_v[tid]; bi = red_i[tid];
            #pragma unroll
            for (int off = 16; off; off >>= 1) {
                float ov = __shfl_down_sync(0xffffffffu, best, off);
                int   oi = __shfl_down_sync(0xffffffffu, bi, off);
                if (ov > best || (ov == best && oi < bi)) { best = ov; bi = oi; }
            }
            if (tid == 0) s_cur = bi;
        }
        __syncthreads();
    }
}

// ---------------- gather new_xyz ----------------
__global__ void newxyz_kernel(const float* __restrict__ xyz, const int* __restrict__ fidx,
                              float* __restrict__ nx, float* __restrict__ out_nx)
{
    int t = blockIdx.x * 256 + threadIdx.x;
    int b = t / SS;
    int j = fidx[t];
    #pragma unroll
    for (int c = 0; c < 3; ++c) {
        float v = xyz[((size_t)b * NN + j) * 3 + c];
        nx[t * 3 + c] = v;
        out_nx[t * 3 + c] = v;
    }
}

// ---------------- ball query: warp per center, ballot compaction ----------------
__global__ __launch_bounds__(256) void ballq_kernel(const float* __restrict__ xyz,
                                                    const float* __restrict__ nx,
                                                    int* __restrict__ idx, float r2, int ns)
{
    int w    = (blockIdx.x * 256 + threadIdx.x) >> 5;   // center id < BS
    int lane = threadIdx.x & 31;
    int b = w >> 11;                                    // / SS
    const float* X = xyz + (size_t)b * NN * 3;
    float cx = nx[w * 3 + 0], cy = nx[w * 3 + 1], cz = nx[w * 3 + 2];
    int* op = idx + (size_t)w * ns;
    int cnt = 0, first = 0;
    for (int base = 0; base < NN; base += 32) {
        int n = base + lane;
        float dx = X[n * 3 + 0] - cx;
        float dy = X[n * 3 + 1] - cy;
        float dz = X[n * 3 + 2] - cz;
        bool hit = dx * dx + dy * dy + dz * dz < r2;
        unsigned m = __ballot_sync(0xffffffffu, hit);
        if (cnt == 0 && m) first = base + __ffs(m) - 1;
        int pos = cnt + __popc(m & ((1u << lane) - 1u));
        if (hit && pos < ns) op[pos] = n;
        cnt += __popc(m);
        if (cnt >= ns) break;
    }
    for (int k = min(cnt, ns) + lane; k < ns; k += 32) op[k] = first;
}

// ---------------- group gather: warp per row ----------------
__global__ void gather_kernel(const float* __restrict__ xyz, const float* __restrict__ feats,
                              const float* __restrict__ nx, const int* __restrict__ idx,
                              int ns, float* __restrict__ G)
{
    int row  = blockIdx.x * 8 + (threadIdx.x >> 5);
    int lane = threadIdx.x & 31;
    int gc = row / ns;
    int b  = gc >> 11;
    int j  = idx[row];
    float* Grow = G + (size_t)row * GST;
    const float* X = xyz + ((size_t)b * NN + j) * 3;
    if (lane < 3) Grow[lane] = X[lane] - nx[gc * 3 + lane];
    const float* F = feats + ((size_t)b * NN + j) * CFEAT;
    Grow[3 + lane]      = F[lane];
    Grow[3 + 32 + lane] = F[32 + lane];
}

// ---------------- GEMM (scalar FFMA, R2-proven shape) + fused column stats ----------------
// block = 128 threads, tile 64 rows x 64 cols; thread = 8 rows x 4 cols
// Y = bnrelu?(A(:,0:M)) @ W[:, c0:c0+64]; per-block colwise (sum,sumsq) -> part[bx]
__global__ __launch_bounds__(128) void mm_kernel(const float* __restrict__ A, int lda, int M,
                                                 const float* __restrict__ W, int ldw,
                                                 const float* __restrict__ mean,
                                                 const float* __restrict__ istd,
                                                 float* __restrict__ Y, int ldy, int K,
                                                 float* __restrict__ part)
{
    __shared__ float As[64][33];
    __shared__ float Ws[32][64];
    int tid = threadIdx.x;
    int tx = tid & 15, ty = tid >> 4;          // 16 col-groups x 8 row-groups
    size_t rowBase = (size_t)blockIdx.x * 64;
    int c0 = blockIdx.y * 64;
    int amc = tid & 31, arr = tid >> 5;        // A loader mapping
    int wc  = tid & 63, wm  = tid >> 6;        // W loader mapping

    float acc[8][4];
    #pragma unroll
    for (int i = 0; i < 8; ++i) { acc[i][0]=0.f; acc[i][1]=0.f; acc[i][2]=0.f; acc[i][3]=0.f; }

    const bool bn = (mean != nullptr);
    for (int m0 = 0; m0 < M; m0 += 32) {
        int rem = min(32, M - m0);
        if (amc < rem) {
            const float* Ap = A + (rowBase + arr) * lda + m0 + amc;
            float mu = 0.f, is = 0.f;
            if (bn) { mu = mean[m0 + amc]; is = istd[m0 + amc]; }
            #pragma unroll
            for (int jj = 0; jj < 16; ++jj) {
                float v = Ap[(size_t)(4 * jj) * lda];
                if (bn) v = fmaxf(0.f, (v - mu) * is);
                As[arr + 4 * jj][amc] = v;
            }
        }
        for (int m = wm; m < rem; m += 2)
            Ws[m][wc] = W[(size_t)(m0 + m) * ldw + c0 + wc];
        __syncthreads();

        #pragma unroll 4
        for (int m = 0; m < rem; ++m) {
            float4 w4 = *(const float4*)&Ws[m][tx * 4];
            #pragma unroll
            for (int i = 0; i < 8; ++i) {
                float a = As[ty + 8 * i][m];
                acc[i][0] = fmaf(a, w4.x, acc[i][0]);
                acc[i][1] = fmaf(a, w4.y, acc[i][1]);
                acc[i][2] = fmaf(a, w4.z, acc[i][2]);
                acc[i][3] = fmaf(a, w4.w, acc[i][3]);
            }
        }
        __syncthreads();
    }

    // write output + per-thread column partial stats
    float cs[4] = {0.f, 0.f, 0.f, 0.f};
    float cq[4] = {0.f, 0.f, 0.f, 0.f};
    #pragma unroll
    for (int i = 0; i < 8; ++i) {
        #pragma unroll
        for (int j = 0; j < 4; ++j) {
            float v = acc[i][j];
            cs[j] += v; cq[j] += v * v;
        }
        float4 v = make_float4(acc[i][0], acc[i][1], acc[i][2], acc[i][3]);
        *(float4*)&Y[(rowBase + ty + 8 * i) * ldy + c0 + tx * 4] = v;
    }

    // reduce partials across the 8 row-groups (reuse As storage: need 1024 floats)
    float* shf = &As[0][0];          // [0..511] sums, [512..1023] sumsq
    #pragma unroll
    for (int j = 0; j < 4; ++j) {
        shf[ty * 64 + tx * 4 + j]       = cs[j];
        shf[512 + ty * 64 + tx * 4 + j] = cq[j];
    }
    __syncthreads();
    if (tid < 64) {
        float s = 0.f, q = 0.f;
        #pragma unroll
        for (int g = 0; g < 8; ++g) { s += shf[g * 64 + tid]; q += shf[512 + g * 64 + tid]; }
        part[((size_t)blockIdx.x * K + c0 + tid) * 2 + 0] = s;
        part[((size_t)blockIdx.x * K + c0 + tid) * 2 + 1] = q;
    }
}

// ---------------- finalize stats (8 independent double chains) ----------------
__global__ void fin_kernel(const float* __restrict__ part, int nb, int rows, int K,
                           float* __restrict__ mean, float* __restrict__ istd)
{
    int c = threadIdx.x;      // < K
    double s[8], q[8];
    #pragma unroll
    for (int u = 0; u < 8; ++u) { s[u] = 0.0; q[u] = 0.0; }
    for (int b = 0; b < nb; b += 8) {
        #pragma unroll
        for (int u = 0; u < 8; ++u) {
            int bb = b + u;
            if (bb < nb) {
                s[u] += part[((size_t)bb * K + c) * 2 + 0];
                q[u] += part[((size_t)bb * K + c) * 2 + 1];
            }
        }
    }
    double S = 0.0, Q = 0.0;
    #pragma unroll
    for (int u = 0; u < 8; ++u) { S += s[u]; Q += q[u]; }
    double n = (double)rows;
    double mu = S / n;
    double var = Q / n - mu * mu;
    if (var < 0.0) var = 0.0;
    mean[c] = (float)mu;
    istd[c] = rsqrtf((float)var + EPSB);
}

// ---------------- BN+ReLU+maxpool over group ----------------
__global__ void maxpool_kernel(const float* __restrict__ Y, int ns,
                               const float* __restrict__ mean, const float* __restrict__ istd,
                               float* __restrict__ Hcat, int off)
{
    int t = blockIdx.x * 256 + threadIdx.x;   // < BS*128
    int c = t & 127;
    int o = t >> 7;
    float mu = mean[c], is = istd[c];
    float m = 0.f;
    for (int k = 0; k < ns; ++k) {
        float v = Y[((size_t)o * ns + k) * 128 + c];
        m = fmaxf(m, fmaxf(0.f, (v - mu) * is));
    }
    Hcat[(size_t)o * 256 + off + c] = m;
}

// ---------------- elementwise BN+ReLU writer (h output) ----------------
__global__ void bnrelu_out_kernel(const float* __restrict__ Yin,
                                  const float* __restrict__ mean, const float* __restrict__ istd,
                                  float* __restrict__ outp)
{
    int t = blockIdx.x * 256 + threadIdx.x;   // < BS*256
    int c = t & 255;
    float v = Yin[t];
    outp[t] = fmaxf(0.f, (v - mean[c]) * istd[c]);
}

// ---------------- cls: warp per row, K=3 + bias ----------------
__global__ void cls_kernel(const float* __restrict__ Yc,
                           const float* __restrict__ mean, const float* __restrict__ istd,
                           const float* __restrict__ W, const float* __restrict__ bias,
                           float* __restrict__ outp)
{
    __shared__ float ws[768];
    int tid = threadIdx.x;
    for (int i = tid; i < 768; i += 256) ws[i] = W[i];
    __syncthreads();
    int warp = tid >> 5, lane = tid & 31;
    int row = blockIdx.x * 8 + warp;
    float a0 = 0.f, a1 = 0.f, a2 = 0.f;
    for (int m = lane; m < 256; m += 32) {
        float a = Yc[(size_t)row * 256 + m];
        a = fmaxf(0.f, (a - mean[m]) * istd[m]);
        a0 = fmaf(a, ws[m * 3 + 0], a0);
        a1 = fmaf(a, ws[m * 3 + 1], a1);
        a2 = fmaf(a, ws[m * 3 + 2], a2);
    }
    #pragma unroll
    for (int off = 16; off; off >>= 1) {
        a0 += __shfl_down_sync(0xffffffffu, a0, off);
        a1 += __shfl_down_sync(0xffffffffu, a1, off);
        a2 += __shfl_down_sync(0xffffffffu, a2, off);
    }
    if (lane == 0) {
        outp[(size_t)row * 3 + 0] = a0 + bias[0];
        outp[(size_t)row * 3 + 1] = a1 + bias[1];
        outp[(size_t)row * 3 + 2] = a2 + bias[2];
    }
}

// ---------------- host driver ----------------
extern "C" void kernel_launch(void* const* d_in, const int* in_sizes, int n_in,
                              void* d_out, int out_size)
{
    (void)in_sizes; (void)n_in; (void)out_size;
    const float* xyz   = (const float*)d_in[0];
    const float* feats = (const float*)d_in[1];
    const float* w00   = (const float*)d_in[2];
    const float* w01   = (const float*)d_in[3];
    const float* w02   = (const float*)d_in[4];
    const float* w10   = (const float*)d_in[5];
    const float* w11   = (const float*)d_in[6];
    const float* w12   = (const float*)d_in[7];
    const float* aggw  = (const float*)d_in[8];
    // d_in[9] = agg_b: cancelled exactly by the following BatchNorm -> unused
    const float* confw = (const float*)d_in[10];
    const float* clsw  = (const float*)d_in[11];
    const float* clsb  = (const float*)d_in[12];

    float* out = (float*)d_out;
    float* out_nx  = out;
    float* out_h   = out + (size_t)BS * 3;
    float* out_cls = out + (size_t)BS * 3 + (size_t)BS * 256;

    int *fps, *idx0, *idx1;
    float *nx, *G, *Ya, *Yb, *Hcat, *Yh, *Yc, *part, *mean, *istd;
    cudaGetSymbolAddress((void**)&fps,  g_fps);
    cudaGetSymbolAddress((void**)&nx,   g_nx);
    cudaGetSymbolAddress((void**)&idx0, g_idx0);
    cudaGetSymbolAddress((void**)&idx1, g_idx1);
    cudaGetSymbolAddress((void**)&G,    g_G);
    cudaGetSymbolAddress((void**)&Ya,   g_Ya);
    cudaGetSymbolAddress((void**)&Yb,   g_Yb);
    cudaGetSymbolAddress((void**)&Hcat, g_Hcat);
    cudaGetSymbolAddress((void**)&Yh,   g_Yh);
    cudaGetSymbolAddress((void**)&Yc,   g_Yc);
    cudaGetSymbolAddress((void**)&part, g_part);
    cudaGetSymbolAddress((void**)&mean, g_mean);
    cudaGetSymbolAddress((void**)&istd, g_istd);

    // sampling + neighborhoods
    fps_kernel<<<BB, 1024>>>(xyz, fps);
    newxyz_kernel<<<BS / 256, 256>>>(xyz, fps, nx, out_nx);
    ballq_kernel<<<BS * 32 / 256, 256>>>(xyz, nx, idx0, 0.4f * 0.4f, NSA0);
    ballq_kernel<<<BS * 32 / 256, 256>>>(xyz, nx, idx1, 0.8f * 0.8f, NSA1);

    // ---- scale 0 (ns=16) ----
    gather_kernel<<<ROWS0 / 8, 256>>>(xyz, feats, nx, idx0, NSA0, G);
    mm_kernel<<<dim3(ROWS0 / 64, 1), 128>>>(G, GST, 67, w00, 64, nullptr, nullptr, Ya, 64, 64, part);
    fin_kernel<<<1, 64>>>(part, ROWS0 / 64, ROWS0, 64, mean, istd);
    mm_kernel<<<dim3(ROWS0 / 64, 1), 128>>>(Ya, 64, 64, w01, 64, mean, istd, Yb, 64, 64, part);
    fin_kernel<<<1, 64>>>(part, ROWS0 / 64, ROWS0, 64, mean, istd);
    mm_kernel<<<dim3(ROWS0 / 64, 2), 128>>>(Yb, 64, 64, w02, 128, mean, istd, Ya, 128, 128, part);
    fin_kernel<<<1, 128>>>(part, ROWS0 / 64, ROWS0, 128, mean, istd);
    maxpool_kernel<<<BS * 128 / 256, 256>>>(Ya, NSA0, mean, istd, Hcat, 0);

    // ---- scale 1 (ns=32) ----
    gather_kernel<<<ROWS1 / 8, 256>>>(xyz, feats, nx, idx1, NSA1, G);
    mm_kernel<<<dim3(ROWS1 / 64, 1), 128>>>(G, GST, 67, w10, 64, nullptr, nullptr, Ya, 64, 64, part);
    fin_kernel<<<1, 64>>>(part, ROWS1 / 64, ROWS1, 64, mean, istd);
    mm_kernel<<<dim3(ROWS1 / 64, 1), 128>>>(Ya, 64, 64, w11, 64, mean, istd, Yb, 64, 64, part);
    fin_kernel<<<1, 64>>>(part, ROWS1 / 64, ROWS1, 64, mean, istd);
    mm_kernel<<<dim3(ROWS1 / 64, 2), 128>>>(Yb, 64, 64, w12, 128, mean, istd, Ya, 128, 128, part);
    fin_kernel<<<1, 128>>>(part, ROWS1 / 64, ROWS1, 128, mean, istd);
    maxpool_kernel<<<BS * 128 / 256, 256>>>(Ya, NSA1, mean, istd, Hcat, 128);

    // ---- head ----
    mm_kernel<<<dim3(BS / 64, 4), 128>>>(Hcat, 256, 256, aggw, 256, nullptr, nullptr, Yh, 256, 256, part);
    fin_kernel<<<1, 256>>>(part, BS / 64, BS, 256, mean, istd);
    bnrelu_out_kernel<<<BS, 256>>>(Yh, mean, istd, out_h);
    mm_kernel<<<dim3(BS / 64, 4), 128>>>(Yh, 256, 256, confw, 256, mean, istd, Yc, 256, 256, part);
    fin_kernel<<<1, 256>>>(part, BS / 64, BS, 256, mean, istd);
    cls_kernel<<<BS / 8, 256>>>(Yc, mean, istd, clsw, clsb, out_cls);
}

// round 5
// speedup vs baseline: 3.6375x; 3.6375x over previous
#include <cuda_runtime.h>
#include <cuda_bf16.h>
#include <math.h>

// ---------------- problem constants ----------------
#define BB   8
#define NN   8192
#define SS   2048
#define CFEAT 64
#define NSA0 16
#define NSA1 32
#define GST  68          // padded row stride for gathered input (67 cols)
#define EPSB 1e-5f
#define NBMAX 8192       // max GEMM grid.x (ROWS1/64)

static constexpr int BS    = BB * SS;            // 16384
static constexpr int ROWS0 = BB * SS * NSA0;     // 262144
static constexpr int ROWS1 = BB * SS * NSA1;     // 524288

// ---------------- scratch (device globals; no allocation allowed) ----------------
__device__ int   g_fps[BS];
__device__ float g_nx[BS * 3];
__device__ int   g_idx0[ROWS0];
__device__ int   g_idx1[ROWS1];
__device__ float g_G[(size_t)ROWS1 * GST];
__device__ float g_Ya[(size_t)ROWS1 * 128];
__device__ float g_Yb[(size_t)ROWS1 * 128];
__device__ float g_Hcat[(size_t)BS * 256];
__device__ float g_Yh[(size_t)BS * 256];
__device__ float g_Yc[(size_t)BS * 256];
__device__ float g_psum[(size_t)256 * NBMAX];    // column-major partial sums
__device__ float g_psq [(size_t)256 * NBMAX];    // column-major partial sumsq
__device__ float g_mean[256];
__device__ float g_istd[256];

// ---------------- FPS: one block per batch ----------------
__global__ __launch_bounds__(1024) void fps_kernel(const float* __restrict__ xyz,
                                                   int* __restrict__ out_idx)
{
    int b = blockIdx.x;
    const float* X = xyz + (size_t)b * NN * 3;
    int tid = threadIdx.x;

    float px[8], py[8], pz[8], dist[8];
    #pragma unroll
    for (int li = 0; li < 8; ++li) {
        int i = tid + 1024 * li;
        px[li] = X[i * 3 + 0];
        py[li] = X[i * 3 + 1];
        pz[li] = X[i * 3 + 2];
        dist[li] = 1e10f;
    }

    __shared__ float red_v[32];
    __shared__ int   red_i[32];
    __shared__ int   s_cur;
    if (tid == 0) s_cur = 0;
    __syncthreads();

    for (int it = 0; it < SS; ++it) {
        int cur = s_cur;
        if (tid == 0) out_idx[(size_t)b * SS + it] = cur;
        float lx = X[cur * 3 + 0];
        float ly = X[cur * 3 + 1];
        float lz = X[cur * 3 + 2];

        float best = -1.0f; int bi = 0;
        #pragma unroll
        for (int li = 0; li < 8; ++li) {
            float dx = px[li] - lx, dy = py[li] - ly, dz = pz[li] - lz;
            float d = dx * dx + dy * dy + dz * dz;
            float dd = fminf(dist[li], d);
            dist[li] = dd;
            if (dd > best) { best = dd; bi = tid + 1024 * li; }
        }
        #pragma unroll
        for (int off = 16; off; off >>= 1) {
            float ov = __shfl_down_sync(0xffffffffu, best, off);
            int   oi = __shfl_down_sync(0xffffffffu, bi, off);
            if (ov > best || (ov == best && oi < bi)) { best = ov; bi = oi; }
        }
        if ((tid & 31) == 0) { red_v[tid >> 5] = best; red_i[tid >> 5] = bi; }
        __syncthreads();
        if (tid < 32) {
            best = red_v[tid]; bi = red_i[tid];
            #pragma unroll
            for (int off = 16; off; off >>= 1) {
                float ov = __shfl_down_sync(0xffffffffu, best, off);
                int   oi = __shfl_down_sync(0xffffffffu, bi, off);
                if (ov > best || (ov == best && oi < bi)) { best = ov; bi = oi; }
            }
            if (tid == 0) s_cur = bi;
        }
        __syncthreads();
    }
}

// ---------------- gather new_xyz ----------------
__global__ void newxyz_kernel(const float* __restrict__ xyz, const int* __restrict__ fidx,
                              float* __restrict__ nx, float* __restrict__ out_nx)
{
    int t = blockIdx.x * 256 + threadIdx.x;
    int b = t / SS;
    int j = fidx[t];
    #pragma unroll
    for (int c = 0; c < 3; ++c) {
        float v = xyz[((size_t)b * NN + j) * 3 + c];
        nx[t * 3 + c] = v;
        out_nx[t * 3 + c] = v;
    }
}

// ---------------- ball query: warp per center, ballot compaction ----------------
__global__ __launch_bounds__(256) void ballq_kernel(const float* __restrict__ xyz,
                                                    const float* __restrict__ nx,
                                                    int* __restrict__ idx, float r2, int ns)
{
    int w    = (blockIdx.x * 256 + threadIdx.x) >> 5;   // center id < BS
    int lane = threadIdx.x & 31;
    int b = w >> 11;                                    // / SS
    const float* X = xyz + (size_t)b * NN * 3;
    float cx = nx[w * 3 + 0], cy = nx[w * 3 + 1], cz = nx[w * 3 + 2];
    int* op = idx + (size_t)w * ns;
    int cnt = 0, first = 0;
    for (int base = 0; base < NN; base += 32) {
        int n = base + lane;
        float dx = X[n * 3 + 0] - cx;
        float dy = X[n * 3 + 1] - cy;
        float dz = X[n * 3 + 2] - cz;
        bool hit = dx * dx + dy * dy + dz * dz < r2;
        unsigned m = __ballot_sync(0xffffffffu, hit);
        if (cnt == 0 && m) first = base + __ffs(m) - 1;
        int pos = cnt + __popc(m & ((1u << lane) - 1u));
        if (hit && pos < ns) op[pos] = n;
        cnt += __popc(m);
        if (cnt >= ns) break;
    }
    for (int k = min(cnt, ns) + lane; k < ns; k += 32) op[k] = first;
}

// ---------------- group gather: warp per row ----------------
__global__ void gather_kernel(const float* __restrict__ xyz, const float* __restrict__ feats,
                              const float* __restrict__ nx, const int* __restrict__ idx,
                              int ns, float* __restrict__ G)
{
    int row  = blockIdx.x * 8 + (threadIdx.x >> 5);
    int lane = threadIdx.x & 31;
    int gc = row / ns;
    int b  = gc >> 11;
    int j  = idx[row];
    float* Grow = G + (size_t)row * GST;
    const float* X = xyz + ((size_t)b * NN + j) * 3;
    if (lane < 3) Grow[lane] = X[lane] - nx[gc * 3 + lane];
    const float* F = feats + ((size_t)b * NN + j) * CFEAT;
    Grow[3 + lane]      = F[lane];
    Grow[3 + 32 + lane] = F[32 + lane];
}

// ---------------- GEMM (scalar FFMA) + fused column stats (column-major partials) ----------------
// block = 128 threads, tile 64 rows x 64 cols; thread = 8 rows x 4 cols
__global__ __launch_bounds__(128) void mm_kernel(const float* __restrict__ A, int lda, int M,
                                                 const float* __restrict__ W, int ldw,
                                                 const float* __restrict__ mean,
                                                 const float* __restrict__ istd,
                                                 float* __restrict__ Y, int ldy,
                                                 float* __restrict__ psum,
                                                 float* __restrict__ psq)
{
    __shared__ float As[64][33];
    __shared__ float Ws[32][64];
    int tid = threadIdx.x;
    int tx = tid & 15, ty = tid >> 4;          // 16 col-groups x 8 row-groups
    size_t rowBase = (size_t)blockIdx.x * 64;
    int c0 = blockIdx.y * 64;
    int amc = tid & 31, arr = tid >> 5;        // A loader mapping
    int wc  = tid & 63, wm  = tid >> 6;        // W loader mapping

    float acc[8][4];
    #pragma unroll
    for (int i = 0; i < 8; ++i) { acc[i][0]=0.f; acc[i][1]=0.f; acc[i][2]=0.f; acc[i][3]=0.f; }

    const bool bn = (mean != nullptr);
    for (int m0 = 0; m0 < M; m0 += 32) {
        int rem = min(32, M - m0);
        if (amc < rem) {
            const float* Ap = A + (rowBase + arr) * lda + m0 + amc;
            float mu = 0.f, is = 0.f;
            if (bn) { mu = mean[m0 + amc]; is = istd[m0 + amc]; }
            #pragma unroll
            for (int jj = 0; jj < 16; ++jj) {
                float v = Ap[(size_t)(4 * jj) * lda];
                if (bn) v = fmaxf(0.f, (v - mu) * is);
                As[arr + 4 * jj][amc] = v;
            }
        }
        for (int m = wm; m < rem; m += 2)
            Ws[m][wc] = W[(size_t)(m0 + m) * ldw + c0 + wc];
        __syncthreads();

        #pragma unroll 4
        for (int m = 0; m < rem; ++m) {
            float4 w4 = *(const float4*)&Ws[m][tx * 4];
            #pragma unroll
            for (int i = 0; i < 8; ++i) {
                float a = As[ty + 8 * i][m];
                acc[i][0] = fmaf(a, w4.x, acc[i][0]);
                acc[i][1] = fmaf(a, w4.y, acc[i][1]);
                acc[i][2] = fmaf(a, w4.z, acc[i][2]);
                acc[i][3] = fmaf(a, w4.w, acc[i][3]);
            }
        }
        __syncthreads();
    }

    // write output + per-thread column partial stats
    float cs[4] = {0.f, 0.f, 0.f, 0.f};
    float cq[4] = {0.f, 0.f, 0.f, 0.f};
    #pragma unroll
    for (int i = 0; i < 8; ++i) {
        #pragma unroll
        for (int j = 0; j < 4; ++j) {
            float v = acc[i][j];
            cs[j] += v; cq[j] += v * v;
        }
        float4 v = make_float4(acc[i][0], acc[i][1], acc[i][2], acc[i][3]);
        *(float4*)&Y[(rowBase + ty + 8 * i) * ldy + c0 + tx * 4] = v;
    }

    // reduce partials across the 8 row-groups (reuse As storage: need 1024 floats)
    float* shf = &As[0][0];          // [0..511] sums, [512..1023] sumsq
    #pragma unroll
    for (int j = 0; j < 4; ++j) {
        shf[ty * 64 + tx * 4 + j]       = cs[j];
        shf[512 + ty * 64 + tx * 4 + j] = cq[j];
    }
    __syncthreads();
    if (tid < 64) {
        float s = 0.f, q = 0.f;
        #pragma unroll
        for (int g = 0; g < 8; ++g) { s += shf[g * 64 + tid]; q += shf[512 + g * 64 + tid]; }
        // column-major: contiguous in blockIdx.x for a fixed channel
        psum[(size_t)(c0 + tid) * NBMAX + blockIdx.x] = s;
        psq [(size_t)(c0 + tid) * NBMAX + blockIdx.x] = q;
    }
}

// ---------------- finalize stats: one block per channel, coalesced reads ----------------
__global__ __launch_bounds__(256) void fin_kernel(const float* __restrict__ psum,
                                                  const float* __restrict__ psq,
                                                  int nb, int rows,
                                                  float* __restrict__ mean,
                                                  float* __restrict__ istd)
{
    int c = blockIdx.x;
    int tid = threadIdx.x;
    const float* sp = psum + (size_t)c * NBMAX;
    const float* qp = psq  + (size_t)c * NBMAX;
    double s = 0.0, q = 0.0;
    for (int b = tid; b < nb; b += 256) { s += sp[b]; q += qp[b]; }
    __shared__ double sh[512];
    sh[tid] = s; sh[256 + tid] = q;
    __syncthreads();
    for (int o = 128; o; o >>= 1) {
        if (tid < o) { sh[tid] += sh[tid + o]; sh[256 + tid] += sh[256 + tid + o]; }
        __syncthreads();
    }
    if (tid == 0) {
        double n = (double)rows;
        double mu = sh[0] / n;
        double var = sh[256] / n - mu * mu;
        if (var < 0.0) var = 0.0;
        mean[c] = (float)mu;
        istd[c] = rsqrtf((float)var + EPSB);
    }
}

// ---------------- BN+ReLU+maxpool over group ----------------
__global__ void maxpool_kernel(const float* __restrict__ Y, int ns,
                               const float* __restrict__ mean, const float* __restrict__ istd,
                               float* __restrict__ Hcat, int off)
{
    int t = blockIdx.x * 256 + threadIdx.x;   // < BS*128
    int c = t & 127;
    int o = t >> 7;
    float mu = mean[c], is = istd[c];
    float m = 0.f;
    for (int k = 0; k < ns; ++k) {
        float v = Y[((size_t)o * ns + k) * 128 + c];
        m = fmaxf(m, fmaxf(0.f, (v - mu) * is));
    }
    Hcat[(size_t)o * 256 + off + c] = m;
}

// ---------------- elementwise BN+ReLU writer (h output) ----------------
__global__ void bnrelu_out_kernel(const float* __restrict__ Yin,
                                  const float* __restrict__ mean, const float* __restrict__ istd,
                                  float* __restrict__ outp)
{
    int t = blockIdx.x * 256 + threadIdx.x;   // < BS*256
    int c = t & 255;
    float v = Yin[t];
    outp[t] = fmaxf(0.f, (v - mean[c]) * istd[c]);
}

// ---------------- cls: warp per row, K=3 + bias ----------------
__global__ void cls_kernel(const float* __restrict__ Yc,
                           const float* __restrict__ mean, const float* __restrict__ istd,
                           const float* __restrict__ W, const float* __restrict__ bias,
                           float* __restrict__ outp)
{
    __shared__ float ws[768];
    int tid = threadIdx.x;
    for (int i = tid; i < 768; i += 256) ws[i] = W[i];
    __syncthreads();
    int warp = tid >> 5, lane = tid & 31;
    int row = blockIdx.x * 8 + warp;
    float a0 = 0.f, a1 = 0.f, a2 = 0.f;
    for (int m = lane; m < 256; m += 32) {
        float a = Yc[(size_t)row * 256 + m];
        a = fmaxf(0.f, (a - mean[m]) * istd[m]);
        a0 = fmaf(a, ws[m * 3 + 0], a0);
        a1 = fmaf(a, ws[m * 3 + 1], a1);
        a2 = fmaf(a, ws[m * 3 + 2], a2);
    }
    #pragma unroll
    for (int off = 16; off; off >>= 1) {
        a0 += __shfl_down_sync(0xffffffffu, a0, off);
        a1 += __shfl_down_sync(0xffffffffu, a1, off);
        a2 += __shfl_down_sync(0xffffffffu, a2, off);
    }
    if (lane == 0) {
        outp[(size_t)row * 3 + 0] = a0 + bias[0];
        outp[(size_t)row * 3 + 1] = a1 + bias[1];
        outp[(size_t)row * 3 + 2] = a2 + bias[2];
    }
}

// ---------------- host driver ----------------
extern "C" void kernel_launch(void* const* d_in, const int* in_sizes, int n_in,
                              void* d_out, int out_size)
{
    (void)in_sizes; (void)n_in; (void)out_size;
    const float* xyz   = (const float*)d_in[0];
    const float* feats = (const float*)d_in[1];
    const float* w00   = (const float*)d_in[2];
    const float* w01   = (const float*)d_in[3];
    const float* w02   = (const float*)d_in[4];
    const float* w10   = (const float*)d_in[5];
    const float* w11   = (const float*)d_in[6];
    const float* w12   = (const float*)d_in[7];
    const float* aggw  = (const float*)d_in[8];
    // d_in[9] = agg_b: cancelled exactly by the following BatchNorm -> unused
    const float* confw = (const float*)d_in[10];
    const float* clsw  = (const float*)d_in[11];
    const float* clsb  = (const float*)d_in[12];

    float* out = (float*)d_out;
    float* out_nx  = out;
    float* out_h   = out + (size_t)BS * 3;
    float* out_cls = out + (size_t)BS * 3 + (size_t)BS * 256;

    int *fps, *idx0, *idx1;
    float *nx, *G, *Ya, *Yb, *Hcat, *Yh, *Yc, *psum, *psq, *mean, *istd;
    cudaGetSymbolAddress((void**)&fps,  g_fps);
    cudaGetSymbolAddress((void**)&nx,   g_nx);
    cudaGetSymbolAddress((void**)&idx0, g_idx0);
    cudaGetSymbolAddress((void**)&idx1, g_idx1);
    cudaGetSymbolAddress((void**)&G,    g_G);
    cudaGetSymbolAddress((void**)&Ya,   g_Ya);
    cudaGetSymbolAddress((void**)&Yb,   g_Yb);
    cudaGetSymbolAddress((void**)&Hcat, g_Hcat);
    cudaGetSymbolAddress((void**)&Yh,   g_Yh);
    cudaGetSymbolAddress((void**)&Yc,   g_Yc);
    cudaGetSymbolAddress((void**)&psum, g_psum);
    cudaGetSymbolAddress((void**)&psq,  g_psq);
    cudaGetSymbolAddress((void**)&mean, g_mean);
    cudaGetSymbolAddress((void**)&istd, g_istd);

    // sampling + neighborhoods
    fps_kernel<<<BB, 1024>>>(xyz, fps);
    newxyz_kernel<<<BS / 256, 256>>>(xyz, fps, nx, out_nx);
    ballq_kernel<<<BS * 32 / 256, 256>>>(xyz, nx, idx0, 0.4f * 0.4f, NSA0);
    ballq_kernel<<<BS * 32 / 256, 256>>>(xyz, nx, idx1, 0.8f * 0.8f, NSA1);

    // ---- scale 0 (ns=16) ----
    gather_kernel<<<ROWS0 / 8, 256>>>(xyz, feats, nx, idx0, NSA0, G);
    mm_kernel<<<dim3(ROWS0 / 64, 1), 128>>>(G, GST, 67, w00, 64, nullptr, nullptr, Ya, 64, psum, psq);
    fin_kernel<<<64, 256>>>(psum, psq, ROWS0 / 64, ROWS0, mean, istd);
    mm_kernel<<<dim3(ROWS0 / 64, 1), 128>>>(Ya, 64, 64, w01, 64, mean, istd, Yb, 64, psum, psq);
    fin_kernel<<<64, 256>>>(psum, psq, ROWS0 / 64, ROWS0, mean, istd);
    mm_kernel<<<dim3(ROWS0 / 64, 2), 128>>>(Yb, 64, 64, w02, 128, mean, istd, Ya, 128, psum, psq);
    fin_kernel<<<128, 256>>>(psum, psq, ROWS0 / 64, ROWS0, mean, istd);
    maxpool_kernel<<<BS * 128 / 256, 256>>>(Ya, NSA0, mean, istd, Hcat, 0);

    // ---- scale 1 (ns=32) ----
    gather_kernel<<<ROWS1 / 8, 256>>>(xyz, feats, nx, idx1, NSA1, G);
    mm_kernel<<<dim3(ROWS1 / 64, 1), 128>>>(G, GST, 67, w10, 64, nullptr, nullptr, Ya, 64, psum, psq);
    fin_kernel<<<64, 256>>>(psum, psq, ROWS1 / 64, ROWS1, mean, istd);
    mm_kernel<<<dim3(ROWS1 / 64, 1), 128>>>(Ya, 64, 64, w11, 64, mean, istd, Yb, 64, psum, psq);
    fin_kernel<<<64, 256>>>(psum, psq, ROWS1 / 64, ROWS1, mean, istd);
    mm_kernel<<<dim3(ROWS1 / 64, 2), 128>>>(Yb, 64, 64, w12, 128, mean, istd, Ya, 128, psum, psq);
    fin_kernel<<<128, 256>>>(psum, psq, ROWS1 / 64, ROWS1, mean, istd);
    maxpool_kernel<<<BS * 128 / 256, 256>>>(Ya, NSA1, mean, istd, Hcat, 128);

    // ---- head ----
    mm_kernel<<<dim3(BS / 64, 4), 128>>>(Hcat, 256, 256, aggw, 256, nullptr, nullptr, Yh, 256, psum, psq);
    fin_kernel<<<256, 256>>>(psum, psq, BS / 64, BS, mean, istd);
    bnrelu_out_kernel<<<BS, 256>>>(Yh, mean, istd, out_h);
    mm_kernel<<<dim3(BS / 64, 4), 128>>>(Yh, 256, 256, confw, 256, mean, istd, Yc, 256, psum, psq);
    fin_kernel<<<256, 256>>>(psum, psq, BS / 64, BS, mean, istd);
    cls_kernel<<<BS / 8, 256>>>(Yc, mean, istd, clsw, clsb, out_cls);
}